// round 1
// baseline (speedup 1.0000x reference)
#include <cuda_runtime.h>
#include <math.h>
#include <stdint.h>

#define Bsz 64
#define Lsz 2048
#define BL (Bsz*Lsz)      // 131072
#define EMBD 128
#define DM 128
#define DI 256
#define DS 16
#define DR 8
#define NL 4

// ---------------- scratch (static device allocations; no cudaMalloc) -------
__device__ float g_xn[BL*DM];          // embed output / rmsnorm output
__device__ float g_x [BL*DM];          // residual stream
__device__ float g_xz[(size_t)BL*512]; // in_proj out: [.. :256]=xi, [256:]=z
__device__ float g_xc[(size_t)BL*DI];  // depthwise conv + silu = u
__device__ float g_dbl[(size_t)BL*40]; // x_proj out (dtlow|B|C)
__device__ float g_pw[(size_t)BL*DI*2];// (p, w=dt*u) interleaved
__device__ float g_y [(size_t)BL*DI];  // scan out / gated out
__device__ float g_wext[DM*384];       // repacked front conv weight
__device__ float g_pool[Bsz*DM];
__device__ float g_h1[Bsz*512];
__device__ float g_h2[Bsz*512];

// ---------------- embed + batchnorm-ish scale -----------------------------
__global__ void k_embed(const int* __restrict__ tok, const float* __restrict__ emb,
                        const float* __restrict__ bnw, const float* __restrict__ bnb)
{
    int idx = blockIdx.x * 256 + threadIdx.x;   // BL*128 total
    if (idx >= BL*EMBD) return;
    int e = idx & 127;
    int t = idx >> 7;
    float s = bnw[e] * rsqrtf(1.0f + 1e-5f);
    g_xn[idx] = emb[tok[t]*EMBD + e] * s + bnb[e];
}

// ---------------- repack front conv weight to [o][tap*128+e] ---------------
__global__ void k_repack(const float* __restrict__ cw)
{
    int idx = blockIdx.x * 256 + threadIdx.x;
    if (idx >= DM*384) return;
    int o = idx / 384, kg = idx % 384;
    int tap = kg >> 7, e = kg & 127;
    g_wext[idx] = cw[(o*EMBD + e)*3 + tap];
}

// ---------------- front conv as implicit GEMM (K=384) + bias + relu --------
__global__ void k_convfront(const float* __restrict__ cb)
{
    __shared__ float As[16][64];
    __shared__ float Ws[16][64];
    int tid = threadIdx.x;
    int tx = tid & 15, ty = tid >> 4;
    long bm = (long)blockIdx.x * 64;
    int bn = blockIdx.y * 64;
    int lrow = tid >> 2, lcol = (tid & 3) * 4;
    float acc[4][4] = {};

    const float* Wp = g_wext + (size_t)(bn + lrow)*384 + lcol;
    for (int kc = 0; kc < 384; kc += 16) {
        int kg = kc + lcol;
        int tap = kg >> 7, e = kg & 127;
        long m = bm + lrow;
        int  l = (int)(m & (Lsz-1));
        int  lsrc = l + tap - 1;
        float4 av = make_float4(0.f,0.f,0.f,0.f);
        if (lsrc >= 0 && lsrc < Lsz)
            av = *(const float4*)(g_xn + (size_t)(m + tap - 1)*EMBD + e);
        float4 wv = *(const float4*)(Wp + kc);
        As[lcol+0][lrow]=av.x; As[lcol+1][lrow]=av.y; As[lcol+2][lrow]=av.z; As[lcol+3][lrow]=av.w;
        Ws[lcol+0][lrow]=wv.x; Ws[lcol+1][lrow]=wv.y; Ws[lcol+2][lrow]=wv.z; Ws[lcol+3][lrow]=wv.w;
        __syncthreads();
        #pragma unroll
        for (int kk = 0; kk < 16; kk++) {
            float4 a4 = *(const float4*)&As[kk][ty*4];
            float4 w4 = *(const float4*)&Ws[kk][tx*4];
            acc[0][0]+=a4.x*w4.x; acc[0][1]+=a4.x*w4.y; acc[0][2]+=a4.x*w4.z; acc[0][3]+=a4.x*w4.w;
            acc[1][0]+=a4.y*w4.x; acc[1][1]+=a4.y*w4.y; acc[1][2]+=a4.y*w4.z; acc[1][3]+=a4.y*w4.w;
            acc[2][0]+=a4.z*w4.x; acc[2][1]+=a4.z*w4.y; acc[2][2]+=a4.z*w4.z; acc[2][3]+=a4.z*w4.w;
            acc[3][0]+=a4.w*w4.x; acc[3][1]+=a4.w*w4.y; acc[3][2]+=a4.w*w4.z; acc[3][3]+=a4.w*w4.w;
        }
        __syncthreads();
    }
    #pragma unroll
    for (int i = 0; i < 4; i++) {
        long row = bm + ty*4 + i;
        #pragma unroll
        for (int j = 0; j < 4; j++) {
            int col = bn + tx*4 + j;
            float v = acc[i][j] + cb[col];
            g_x[row*DM + col] = fmaxf(v, 0.f);
        }
    }
}

// ---------------- generic fp32 GEMM: C = act(A[M,K] * W[N,K]^T + bias + res)
__global__ void k_gemm(const float* __restrict__ A, const float* __restrict__ W,
                       const float* __restrict__ bias, const float* __restrict__ res,
                       float* __restrict__ C, int N, int K, int act)
{
    __shared__ float As[16][64];
    __shared__ float Ws[16][64];
    int tid = threadIdx.x;
    int tx = tid & 15, ty = tid >> 4;
    long bm = (long)blockIdx.x * 64;
    int bn = blockIdx.y * 64;
    int lrow = tid >> 2, lcol = (tid & 3) * 4;
    const float* Ap = A + (bm + lrow)*(size_t)K + lcol;
    int nrow = bn + lrow;
    const float* Wp = (nrow < N) ? (W + (size_t)nrow*K + lcol) : (const float*)0;
    float acc[4][4] = {};
    for (int kc = 0; kc < K; kc += 16) {
        float4 av = *(const float4*)(Ap + kc);
        float4 wv = make_float4(0.f,0.f,0.f,0.f);
        if (Wp) wv = *(const float4*)(Wp + kc);
        As[lcol+0][lrow]=av.x; As[lcol+1][lrow]=av.y; As[lcol+2][lrow]=av.z; As[lcol+3][lrow]=av.w;
        Ws[lcol+0][lrow]=wv.x; Ws[lcol+1][lrow]=wv.y; Ws[lcol+2][lrow]=wv.z; Ws[lcol+3][lrow]=wv.w;
        __syncthreads();
        #pragma unroll
        for (int kk = 0; kk < 16; kk++) {
            float4 a4 = *(const float4*)&As[kk][ty*4];
            float4 w4 = *(const float4*)&Ws[kk][tx*4];
            acc[0][0]+=a4.x*w4.x; acc[0][1]+=a4.x*w4.y; acc[0][2]+=a4.x*w4.z; acc[0][3]+=a4.x*w4.w;
            acc[1][0]+=a4.y*w4.x; acc[1][1]+=a4.y*w4.y; acc[1][2]+=a4.y*w4.z; acc[1][3]+=a4.y*w4.w;
            acc[2][0]+=a4.z*w4.x; acc[2][1]+=a4.z*w4.y; acc[2][2]+=a4.z*w4.z; acc[2][3]+=a4.z*w4.w;
            acc[3][0]+=a4.w*w4.x; acc[3][1]+=a4.w*w4.y; acc[3][2]+=a4.w*w4.z; acc[3][3]+=a4.w*w4.w;
        }
        __syncthreads();
    }
    #pragma unroll
    for (int i = 0; i < 4; i++) {
        long row = bm + ty*4 + i;
        #pragma unroll
        for (int j = 0; j < 4; j++) {
            int col = bn + tx*4 + j;
            if (col < N) {
                float v = acc[i][j];
                if (bias) v += bias[col];
                if (res)  v += res[row*(size_t)N + col];
                if (act)  v = fmaxf(v, 0.f);
                C[row*(size_t)N + col] = v;
            }
        }
    }
}

// ---------------- rmsnorm over DM=128 --------------------------------------
__global__ void k_rms(const float* __restrict__ nw)
{
    long rowid = blockIdx.x;
    int e = threadIdx.x;
    float v = g_x[rowid*DM + e];
    float ss = v*v;
    #pragma unroll
    for (int o = 16; o; o >>= 1) ss += __shfl_xor_sync(0xffffffffu, ss, o);
    __shared__ float sr[4];
    if ((e & 31) == 0) sr[e >> 5] = ss;
    __syncthreads();
    float tot = sr[0] + sr[1] + sr[2] + sr[3];
    g_xn[rowid*DM + e] = v * rsqrtf(tot * (1.f/DM) + 1e-5f) * nw[e];
}

// ---------------- depthwise causal conv (k=4) + silu -----------------------
__global__ void k_dwconv(const float* __restrict__ w, const float* __restrict__ bias)
{
    int b  = blockIdx.y;
    int l0 = blockIdx.x * 16;
    int d  = threadIdx.x;
    float w0 = w[d*4+0], w1 = w[d*4+1], w2 = w[d*4+2], w3 = w[d*4+3];
    float bb = bias[d];
    const float* xp = g_xz + (size_t)b*Lsz*512 + d;   // xi lane d
    float v[19];
    #pragma unroll
    for (int j = 0; j < 19; j++) {
        int ls = l0 + j - 3;
        v[j] = (ls >= 0) ? xp[(size_t)ls*512] : 0.f;
    }
    float* op = g_xc + ((size_t)b*Lsz + l0)*DI + d;
    #pragma unroll
    for (int t = 0; t < 16; t++) {
        float a = v[t]*w0 + v[t+1]*w1 + v[t+2]*w2 + v[t+3]*w3 + bb;
        op[(size_t)t*DI] = a / (1.f + __expf(-a));
    }
}

// ---------------- dt: a = dlow . dtw + b; emit p=exp(-softplus(a)), w=dt*u --
__global__ void k_dt(const float* __restrict__ dtw, const float* __restrict__ dtb)
{
    long bl = blockIdx.x;
    int d = threadIdx.x;
    const float* row = g_dbl + bl*40;
    float4 r0 = *(const float4*)(row);
    float4 r1 = *(const float4*)(row + 4);
    const float4* wp = (const float4*)(dtw + d*8);
    float4 w0 = wp[0], w1 = wp[1];
    float a = dtb[d] + r0.x*w0.x + r0.y*w0.y + r0.z*w0.z + r0.w*w0.w
                     + r1.x*w1.x + r1.y*w1.y + r1.z*w1.z + r1.w*w1.w;
    float dt = (a > 15.f) ? a : log1pf(__expf(a));
    float p  = 1.f / (1.f + __expf(a));     // = exp(-softplus(a)) = exp(-dt)
    float u  = g_xc[bl*DI + d];
    float2* o = (float2*)g_pw + bl*DI + d;
    *o = make_float2(p, dt*u);
}

// ---------------- selective scan (sequential over L) -----------------------
__global__ void k_scan(const float* __restrict__ Alog)
{
    int b = blockIdx.x;
    int d = blockIdx.y * 64 + threadIdx.x;

    // detect A_s = -(s+1) structure (true for this model) -> MUFU-free path
    bool fast = true;
    float a[DS];
    #pragma unroll
    for (int s = 0; s < DS; s++) {
        a[s] = -expf(Alog[d*DS + s]);
        if (fabsf(a[s] + (float)(s+1)) > 1e-4f*(float)(s+1)) fast = false;
    }

    float h[DS];
    #pragma unroll
    for (int s = 0; s < DS; s++) h[s] = 0.f;

    const float*  bcp = g_dbl + (size_t)b*Lsz*40;
    const float2* pwp = (const float2*)g_pw + ((size_t)b*Lsz*DI + d);
    float*        yp  = g_y + (size_t)b*Lsz*DI + d;

    if (fast) {
        for (int l = 0; l < Lsz; l++) {
            float2 pv = pwp[(size_t)l*DI];
            const float4* B4 = (const float4*)(bcp + (size_t)l*40 + 8);
            const float4* C4 = (const float4*)(bcp + (size_t)l*40 + 24);
            float p = pv.x, w = pv.y;
            float p2 = p*p;
            float q1 = p, q2 = p2, q3 = p2*p, q4 = p2*p2;
            float y0 = 0.f, y1 = 0.f, y2 = 0.f, y3 = 0.f;
            float base = 1.f;
            #pragma unroll
            for (int g = 0; g < 4; g++) {
                float4 Bv = B4[g], Cv = C4[g];
                float d1 = base*q1, d2 = base*q2, d3 = base*q3, d4 = base*q4;
                h[4*g+0] = d1*h[4*g+0] + w*Bv.x;
                h[4*g+1] = d2*h[4*g+1] + w*Bv.y;
                h[4*g+2] = d3*h[4*g+2] + w*Bv.z;
                h[4*g+3] = d4*h[4*g+3] + w*Bv.w;
                y0 += h[4*g+0]*Cv.x;
                y1 += h[4*g+1]*Cv.y;
                y2 += h[4*g+2]*Cv.z;
                y3 += h[4*g+3]*Cv.w;
                base = base*q4;
            }
            yp[(size_t)l*DI] = (y0+y1) + (y2+y3);
        }
    } else {
        for (int l = 0; l < Lsz; l++) {
            float2 pv = pwp[(size_t)l*DI];
            float w = pv.y;
            float dt = -__logf(fmaxf(pv.x, 1e-38f));
            float yacc = 0.f;
            #pragma unroll
            for (int s = 0; s < DS; s++) {
                float dA = __expf(dt * a[s]);
                h[s] = dA*h[s] + w*bcp[(size_t)l*40 + 8 + s];
                yacc += h[s]*bcp[(size_t)l*40 + 24 + s];
            }
            yp[(size_t)l*DI] = yacc;
        }
    }
}

// ---------------- gate: y = (y + u*D) * silu(z) -----------------------------
__global__ void k_gate(const float* __restrict__ Dp)
{
    long idx = (long)blockIdx.x * 256 + threadIdx.x;  // BL*256 total
    int  d  = (int)(idx & 255);
    long bl = idx >> 8;
    float u = g_xc[idx];
    float z = g_xz[bl*512 + 256 + d];
    float y = g_y[idx] + u*Dp[d];
    g_y[idx] = y * (z / (1.f + __expf(-z)));
}

// ---------------- masked mean pool over L -----------------------------------
__global__ void k_pool(const float* __restrict__ mask)
{
    int b = blockIdx.x;
    int e = threadIdx.x;
    const float* xp = g_x + (size_t)b*Lsz*DM + e;
    const float* mp = mask + (size_t)b*Lsz;
    float acc = 0.f, ms = 0.f;
    for (int l = 0; l < Lsz; l++) {
        float m = mp[l];
        acc += xp[(size_t)l*DM] * m;
        ms  += m;
    }
    g_pool[b*DM + e] = acc / fmaxf(ms, 1e-9f);
}

// ---------------- final 512 -> 3 head ---------------------------------------
__global__ void k_mlp3(const float* __restrict__ w, const float* __restrict__ bias,
                       float* __restrict__ out)
{
    int t = threadIdx.x;
    if (t >= Bsz*3) return;
    int bb = t / 3, n = t - bb*3;
    const float* hp = g_h2 + bb*512;
    const float* wp = w + n*512;
    float acc = bias[n];
    for (int k = 0; k < 512; k++) acc += hp[k]*wp[k];
    out[bb*3 + n] = acc;
}

// ---------------- launch ----------------------------------------------------
extern "C" void kernel_launch(void* const* d_in, const int* in_sizes, int n_in,
                              void* d_out, int out_size)
{
    const int*   tokens = (const int*)  d_in[0];
    const float* mask   = (const float*)d_in[1];
    const float* emb    = (const float*)d_in[2];
    const float* bn_w   = (const float*)d_in[3];
    const float* bn_b   = (const float*)d_in[4];
    const float* conv_w = (const float*)d_in[5];
    const float* conv_b = (const float*)d_in[6];
    const float* in_w   = (const float*)d_in[7];
    const float* c1_w   = (const float*)d_in[8];
    const float* c1_b   = (const float*)d_in[9];
    const float* xp_w   = (const float*)d_in[10];
    const float* dtp_w  = (const float*)d_in[11];
    const float* dtp_b  = (const float*)d_in[12];
    const float* A_log  = (const float*)d_in[13];
    const float* D_p    = (const float*)d_in[14];
    const float* out_w  = (const float*)d_in[15];
    const float* norm_w = (const float*)d_in[16];
    const float* l1w    = (const float*)d_in[17];
    const float* l1b    = (const float*)d_in[18];
    const float* l2w    = (const float*)d_in[19];
    const float* l2b    = (const float*)d_in[20];
    const float* l3w    = (const float*)d_in[21];
    const float* l3b    = (const float*)d_in[22];
    float* out = (float*)d_out;

    float *p_xn, *p_x, *p_xz, *p_xc, *p_dbl, *p_y, *p_pool, *p_h1, *p_h2;
    cudaGetSymbolAddress((void**)&p_xn,  g_xn);
    cudaGetSymbolAddress((void**)&p_x,   g_x);
    cudaGetSymbolAddress((void**)&p_xz,  g_xz);
    cudaGetSymbolAddress((void**)&p_xc,  g_xc);
    cudaGetSymbolAddress((void**)&p_dbl, g_dbl);
    cudaGetSymbolAddress((void**)&p_y,   g_y);
    cudaGetSymbolAddress((void**)&p_pool,g_pool);
    cudaGetSymbolAddress((void**)&p_h1,  g_h1);
    cudaGetSymbolAddress((void**)&p_h2,  g_h2);

    k_embed<<<BL*EMBD/256, 256>>>(tokens, emb, bn_w, bn_b);
    k_repack<<<(DM*384 + 255)/256, 256>>>(conv_w);
    k_convfront<<<dim3(BL/64, DM/64), 256>>>(conv_b);

    for (int i = 0; i < NL; i++) {
        k_rms<<<BL, 128>>>(norm_w + (size_t)i*DM);
        k_gemm<<<dim3(BL/64, 512/64), 256>>>(p_xn, in_w + (size_t)i*512*DM,
                                             (const float*)0, (const float*)0,
                                             p_xz, 512, DM, 0);
        k_dwconv<<<dim3(Lsz/16, Bsz), 256>>>(c1_w + (size_t)i*DI*4, c1_b + (size_t)i*DI);
        k_gemm<<<dim3(BL/64, 1), 256>>>(p_xc, xp_w + (size_t)i*40*DI,
                                        (const float*)0, (const float*)0,
                                        p_dbl, 40, DI, 0);
        k_dt<<<BL, 256>>>(dtp_w + (size_t)i*DI*DR, dtp_b + (size_t)i*DI);
        k_scan<<<dim3(Bsz, DI/64), 64>>>(A_log + (size_t)i*DI*DS);
        k_gate<<<BL, 256>>>(D_p + (size_t)i*DI);
        k_gemm<<<dim3(BL/64, DM/64), 256>>>(p_y, out_w + (size_t)i*DM*DI,
                                            (const float*)0, p_x,
                                            p_x, DM, DI, 0);
    }

    k_pool<<<Bsz, 128>>>(mask);
    k_gemm<<<dim3(1, 512/64), 256>>>(p_pool, l1w, l1b, (const float*)0, p_h1, 512, DM, 1);
    k_gemm<<<dim3(1, 512/64), 256>>>(p_h1,   l2w, l2b, (const float*)0, p_h2, 512, 512, 1);
    k_mlp3<<<1, 256>>>(l3w, l3b, out);
}

// round 3
// speedup vs baseline: 1.3417x; 1.3417x over previous
#include <cuda_runtime.h>
#include <cuda_bf16.h>
#include <math.h>
#include <stdint.h>

#define Bsz 64
#define Lsz 2048
#define BL (Bsz*Lsz)      // 131072
#define EMBD 128
#define DM 128
#define DI 256
#define DS 16
#define DR 8
#define NL 4

// ---------------- scratch (static device arrays; no cudaMalloc) ------------
__device__ float g_xn[BL*DM];          // embed output / rmsnorm output
__device__ float g_x [BL*DM];          // residual stream
__device__ float g_xz[(size_t)BL*512]; // in_proj out: [..:256]=xi, [256:]=z
__device__ float g_xc[(size_t)BL*DI];  // depthwise conv + silu = u
__device__ float g_dbl[(size_t)BL*40]; // x_proj out (dtlow|B|C)
__device__ float g_pw[(size_t)BL*DI*2];// (p, w=dt*u) interleaved
__device__ float g_y [(size_t)BL*DI];  // scan out
__device__ float g_wext[DM*384];       // repacked front conv weight
__device__ float g_pool[Bsz*DM];
__device__ float g_poolp[Bsz*16*DM];
__device__ float g_msum[Bsz*16];
__device__ float g_h1[Bsz*512];
__device__ float g_h2[Bsz*512];

// =================== mma.sync helpers (portable sm_80+ PTX) ================
__device__ __forceinline__ uint32_t s2u(const void* p) {
    uint32_t a;
    asm("{ .reg .u64 t; cvta.to.shared.u64 t, %1; cvt.u32.u64 %0, t; }" : "=r"(a) : "l"(p));
    return a;
}
__device__ __forceinline__ uint32_t swz(uint32_t off) {   // SW128 swizzle
    return off ^ ((off >> 3) & 0x70);
}
__device__ __forceinline__ void ldm_x4(uint32_t* r, uint32_t addr) {
    asm volatile("ldmatrix.sync.aligned.m8n8.x4.shared.b16 {%0,%1,%2,%3}, [%4];"
        : "=r"(r[0]), "=r"(r[1]), "=r"(r[2]), "=r"(r[3]) : "r"(addr));
}
__device__ __forceinline__ void mma_bf16(float* d, const uint32_t* a, const uint32_t* b) {
    asm volatile(
        "mma.sync.aligned.m16n8k16.row.col.f32.bf16.bf16.f32 "
        "{%0,%1,%2,%3}, {%4,%5,%6,%7}, {%8,%9}, {%0,%1,%2,%3};"
        : "+f"(d[0]), "+f"(d[1]), "+f"(d[2]), "+f"(d[3])
        : "r"(a[0]), "r"(a[1]), "r"(a[2]), "r"(a[3]), "r"(b[0]), "r"(b[1]));
}
__device__ __forceinline__ uint32_t pack_bf2(__nv_bfloat16 a, __nv_bfloat16 b) {
    unsigned short x = *(unsigned short*)&a, y = *(unsigned short*)&b;
    return (uint32_t)x | ((uint32_t)y << 16);
}
// convert float4 -> bf16 hi/lo and store swizzled into two smem tiles (128B rows)
__device__ __forceinline__ void stash(char* hi, char* lo, int row, int col4, float4 v) {
    __nv_bfloat16 h0 = __float2bfloat16(v.x), h1 = __float2bfloat16(v.y);
    __nv_bfloat16 h2 = __float2bfloat16(v.z), h3 = __float2bfloat16(v.w);
    float l0 = v.x - __bfloat162float(h0), l1 = v.y - __bfloat162float(h1);
    float l2 = v.z - __bfloat162float(h2), l3 = v.w - __bfloat162float(h3);
    __nv_bfloat16 g0 = __float2bfloat16(l0), g1 = __float2bfloat16(l1);
    __nv_bfloat16 g2 = __float2bfloat16(l2), g3 = __float2bfloat16(l3);
    uint32_t off = (uint32_t)(row * 128 + col4 * 2);
    uint32_t sw = swz(off);
    *(uint2*)(hi + sw) = make_uint2(pack_bf2(h0, h1), pack_bf2(h2, h3));
    *(uint2*)(lo + sw) = make_uint2(pack_bf2(g0, g1), pack_bf2(g2, g3));
}

// ============== tensor-core split-bf16 GEMM via mma.sync ====================
// C[M x Nreal] = epi(A[M,K] * W[Nreal,K]^T); block tile 128x128, K-chunk 64
// amode: 0 = plain A; 1 = gated A from g_y,g_xc,g_xz,Dp; 2 = front conv from g_xn
__global__ void __launch_bounds__(256, 2)
k_hmm(const float* __restrict__ A, const float* __restrict__ W,
      const float* __restrict__ Dp, const float* __restrict__ bias,
      const float* __restrict__ res, float* __restrict__ C,
      int K, int ldC, int Nreal, int Nstore, int amode, int relu)
{
    extern __shared__ char smem[];
    char* AH = smem;            // 128x64 bf16 = 16KB
    char* AL = smem + 16384;
    char* BH = smem + 32768;
    char* BLo = smem + 49152;
    uint32_t uAH = s2u(AH), uAL = s2u(AL), uBH = s2u(BH), uBL = s2u(BLo);

    int tid = threadIdx.x;
    int wid = tid >> 5, lane = tid & 31;
    int mw = wid & 3, nw = wid >> 2;          // 4 x 2 warp grid
    long bm = (long)blockIdx.x * 128;
    int bn = blockIdx.y * 128;

    // staging mapping
    int cg = tid & 15, rb = tid >> 4;
    int col4 = cg * 4;

    // ldmatrix lane address components
    int lmat = lane >> 3, lrow = lane & 7;
    int a_row = mw * 32 + (lmat & 1) * 8 + lrow;   // + f*16
    int a_koff = (lmat >> 1) * 16;
    int b_row = nw * 64 + (lmat >> 1) * 8 + lrow;  // + np*16
    int b_koff = (lmat & 1) * 16;

    float acc[2][8][4];
    #pragma unroll
    for (int f = 0; f < 2; f++)
        #pragma unroll
        for (int n = 0; n < 8; n++)
            #pragma unroll
            for (int j = 0; j < 4; j++) acc[f][n][j] = 0.f;

    int KB = K / 64;
    for (int kb = 0; kb < KB; kb++) {
        // ---- stage A tile (128 x 64) ----
        #pragma unroll
        for (int i = 0; i < 8; i++) {
            int row = rb + i * 16;
            float4 v;
            if (amode == 0) {
                v = *(const float4*)(A + (size_t)(bm + row) * K + kb * 64 + col4);
            } else if (amode == 1) {
                size_t off = (size_t)(bm + row) * 256 + kb * 64 + col4;
                float4 yv = *(const float4*)(g_y + off);
                float4 uv = *(const float4*)(g_xc + off);
                float4 zv = *(const float4*)(g_xz + (size_t)(bm + row) * 512 + 256 + kb * 64 + col4);
                float4 dv = *(const float4*)(Dp + kb * 64 + col4);
                v.x = (yv.x + uv.x * dv.x) * (zv.x / (1.f + __expf(-zv.x)));
                v.y = (yv.y + uv.y * dv.y) * (zv.y / (1.f + __expf(-zv.y)));
                v.z = (yv.z + uv.z * dv.z) * (zv.z / (1.f + __expf(-zv.z)));
                v.w = (yv.w + uv.w * dv.w) * (zv.w / (1.f + __expf(-zv.w)));
            } else {
                int tap = kb >> 1;
                int e = (kb & 1) * 64 + col4;
                long m = bm + row;
                int l = (int)(m & (Lsz - 1));
                int lsrc = l + tap - 1;
                if (lsrc >= 0 && lsrc < Lsz)
                    v = *(const float4*)(A + (size_t)(m + tap - 1) * 128 + e);
                else
                    v = make_float4(0.f, 0.f, 0.f, 0.f);
            }
            stash(AH, AL, row, col4, v);
        }
        // ---- stage B tile (128 x 64) ----
        #pragma unroll
        for (int i = 0; i < 8; i++) {
            int n = rb + i * 16;
            float4 v = make_float4(0.f, 0.f, 0.f, 0.f);
            if (bn + n < Nreal)
                v = *(const float4*)(W + (size_t)(bn + n) * K + kb * 64 + col4);
            stash(BH, BLo, n, col4, v);
        }
        __syncthreads();

        // ---- compute 4 k16 steps ----
        #pragma unroll
        for (int kk = 0; kk < 4; kk++) {
            uint32_t ah[2][4], al[2][4];
            #pragma unroll
            for (int f = 0; f < 2; f++) {
                uint32_t off = (uint32_t)((a_row + f * 16) * 128 + kk * 32 + a_koff);
                uint32_t sw = swz(off);
                ldm_x4(ah[f], uAH + sw);
                ldm_x4(al[f], uAL + sw);
            }
            #pragma unroll
            for (int np = 0; np < 4; np++) {
                uint32_t bh[4], bl[4];
                uint32_t off = (uint32_t)((b_row + np * 16) * 128 + kk * 32 + b_koff);
                uint32_t sw = swz(off);
                ldm_x4(bh, uBH + sw);
                ldm_x4(bl, uBL + sw);
                #pragma unroll
                for (int f = 0; f < 2; f++) {
                    mma_bf16(acc[f][2*np+0], ah[f], bh + 0);
                    mma_bf16(acc[f][2*np+0], ah[f], bl + 0);
                    mma_bf16(acc[f][2*np+0], al[f], bh + 0);
                    mma_bf16(acc[f][2*np+1], ah[f], bh + 2);
                    mma_bf16(acc[f][2*np+1], ah[f], bl + 2);
                    mma_bf16(acc[f][2*np+1], al[f], bh + 2);
                }
            }
        }
        __syncthreads();
    }

    // ---- epilogue: write accumulators ----
    int g = lane >> 2, t2 = (lane & 3) * 2;
    #pragma unroll
    for (int f = 0; f < 2; f++) {
        #pragma unroll
        for (int nt = 0; nt < 8; nt++) {
            int col = bn + nw * 64 + nt * 8 + t2;
            if (col >= Nstore) continue;
            long r0 = bm + mw * 32 + f * 16 + g;
            long r1 = r0 + 8;
            float2 d0 = make_float2(acc[f][nt][0], acc[f][nt][1]);
            float2 d1 = make_float2(acc[f][nt][2], acc[f][nt][3]);
            if (bias) { float b0 = bias[col], b1 = bias[col+1];
                        d0.x += b0; d0.y += b1; d1.x += b0; d1.y += b1; }
            if (res) {
                float2 q0 = *(const float2*)(res + (size_t)r0 * ldC + col);
                float2 q1 = *(const float2*)(res + (size_t)r1 * ldC + col);
                d0.x += q0.x; d0.y += q0.y; d1.x += q1.x; d1.y += q1.y;
            }
            if (relu) {
                d0.x = fmaxf(d0.x, 0.f); d0.y = fmaxf(d0.y, 0.f);
                d1.x = fmaxf(d1.x, 0.f); d1.y = fmaxf(d1.y, 0.f);
            }
            *(float2*)(C + (size_t)r0 * ldC + col) = d0;
            *(float2*)(C + (size_t)r1 * ldC + col) = d1;
        }
    }
}

// ---------------- embed + batchnorm-ish scale -----------------------------
__global__ void k_embed(const int* __restrict__ tok, const float* __restrict__ emb,
                        const float* __restrict__ bnw, const float* __restrict__ bnb)
{
    int idx = blockIdx.x * 256 + threadIdx.x;
    if (idx >= BL * EMBD) return;
    int e = idx & 127;
    int t = idx >> 7;
    float s = bnw[e] * rsqrtf(1.0f + 1e-5f);
    g_xn[idx] = emb[tok[t] * EMBD + e] * s + bnb[e];
}

// ---------------- repack front conv weight to [o][tap*128+e] ---------------
__global__ void k_repack(const float* __restrict__ cw)
{
    int idx = blockIdx.x * 256 + threadIdx.x;
    if (idx >= DM * 384) return;
    int o = idx / 384, kg = idx % 384;
    int tap = kg >> 7, e = kg & 127;
    g_wext[idx] = cw[(o * EMBD + e) * 3 + tap];
}

// ---------------- rmsnorm: warp per row, float4 ----------------------------
__global__ void k_rms(const float* __restrict__ nw)
{
    int w = threadIdx.x >> 5, lid = threadIdx.x & 31;
    long row = (long)blockIdx.x * 8 + w;
    float4 v = ((const float4*)(g_x + row * DM))[lid];
    float ss = v.x * v.x + v.y * v.y + v.z * v.z + v.w * v.w;
    #pragma unroll
    for (int o = 16; o; o >>= 1) ss += __shfl_xor_sync(0xffffffffu, ss, o);
    float r = rsqrtf(ss * (1.f / DM) + 1e-5f);
    float4 wv = ((const float4*)nw)[lid];
    float4 ov = make_float4(v.x * r * wv.x, v.y * r * wv.y, v.z * r * wv.z, v.w * r * wv.w);
    ((float4*)(g_xn + row * DM))[lid] = ov;
}

// ---------------- generic fp32 GEMM (small head layers) --------------------
__global__ void k_gemm(const float* __restrict__ A, const float* __restrict__ W,
                       const float* __restrict__ bias, const float* __restrict__ res,
                       float* __restrict__ C, int N, int K, int act)
{
    __shared__ float As[16][64];
    __shared__ float Ws[16][64];
    int tid = threadIdx.x;
    int tx = tid & 15, ty = tid >> 4;
    long bm = (long)blockIdx.x * 64;
    int bn = blockIdx.y * 64;
    int lrow = tid >> 2, lcol = (tid & 3) * 4;
    const float* Ap = A + (bm + lrow) * (size_t)K + lcol;
    int nrow = bn + lrow;
    const float* Wp = (nrow < N) ? (W + (size_t)nrow * K + lcol) : (const float*)0;
    float acc[4][4] = {};
    for (int kc = 0; kc < K; kc += 16) {
        float4 av = *(const float4*)(Ap + kc);
        float4 wv = make_float4(0.f, 0.f, 0.f, 0.f);
        if (Wp) wv = *(const float4*)(Wp + kc);
        As[lcol+0][lrow]=av.x; As[lcol+1][lrow]=av.y; As[lcol+2][lrow]=av.z; As[lcol+3][lrow]=av.w;
        Ws[lcol+0][lrow]=wv.x; Ws[lcol+1][lrow]=wv.y; Ws[lcol+2][lrow]=wv.z; Ws[lcol+3][lrow]=wv.w;
        __syncthreads();
        #pragma unroll
        for (int kk = 0; kk < 16; kk++) {
            float4 a4 = *(const float4*)&As[kk][ty*4];
            float4 w4 = *(const float4*)&Ws[kk][tx*4];
            acc[0][0]+=a4.x*w4.x; acc[0][1]+=a4.x*w4.y; acc[0][2]+=a4.x*w4.z; acc[0][3]+=a4.x*w4.w;
            acc[1][0]+=a4.y*w4.x; acc[1][1]+=a4.y*w4.y; acc[1][2]+=a4.y*w4.z; acc[1][3]+=a4.y*w4.w;
            acc[2][0]+=a4.z*w4.x; acc[2][1]+=a4.z*w4.y; acc[2][2]+=a4.z*w4.z; acc[2][3]+=a4.z*w4.w;
            acc[3][0]+=a4.w*w4.x; acc[3][1]+=a4.w*w4.y; acc[3][2]+=a4.w*w4.z; acc[3][3]+=a4.w*w4.w;
        }
        __syncthreads();
    }
    #pragma unroll
    for (int i = 0; i < 4; i++) {
        long row = bm + ty * 4 + i;
        #pragma unroll
        for (int j = 0; j < 4; j++) {
            int col = bn + tx * 4 + j;
            if (col < N) {
                float v = acc[i][j];
                if (bias) v += bias[col];
                if (res)  v += res[row * (size_t)N + col];
                if (act)  v = fmaxf(v, 0.f);
                C[row * (size_t)N + col] = v;
            }
        }
    }
}

// ---------------- depthwise causal conv (k=4) + silu -----------------------
__global__ void k_dwconv(const float* __restrict__ w, const float* __restrict__ bias)
{
    int b  = blockIdx.y;
    int l0 = blockIdx.x * 16;
    int d  = threadIdx.x;
    float w0 = w[d*4+0], w1 = w[d*4+1], w2 = w[d*4+2], w3 = w[d*4+3];
    float bb = bias[d];
    const float* xp = g_xz + (size_t)b * Lsz * 512 + d;
    float v[19];
    #pragma unroll
    for (int j = 0; j < 19; j++) {
        int ls = l0 + j - 3;
        v[j] = (ls >= 0) ? xp[(size_t)ls * 512] : 0.f;
    }
    float* op = g_xc + ((size_t)b * Lsz + l0) * DI + d;
    #pragma unroll
    for (int t = 0; t < 16; t++) {
        float a = v[t]*w0 + v[t+1]*w1 + v[t+2]*w2 + v[t+3]*w3 + bb;
        op[(size_t)t * DI] = a / (1.f + __expf(-a));
    }
}

// ---------------- dt: a = dlow . dtw + b; emit p=exp(-softplus(a)), w=dt*u --
__global__ void k_dt(const float* __restrict__ dtw, const float* __restrict__ dtb)
{
    long bl = blockIdx.x;
    int d = threadIdx.x;
    const float* row = g_dbl + bl * 40;
    float4 r0 = *(const float4*)(row);
    float4 r1 = *(const float4*)(row + 4);
    const float4* wp = (const float4*)(dtw + d * 8);
    float4 w0 = wp[0], w1 = wp[1];
    float a = dtb[d] + r0.x*w0.x + r0.y*w0.y + r0.z*w0.z + r0.w*w0.w
                     + r1.x*w1.x + r1.y*w1.y + r1.z*w1.z + r1.w*w1.w;
    float dt = (a > 15.f) ? a : log1pf(__expf(a));
    float p  = 1.f / (1.f + __expf(a));
    float u  = g_xc[bl * DI + d];
    float2* o = (float2*)g_pw + bl * DI + d;
    *o = make_float2(p, dt * u);
}

// ---------------- selective scan (sequential over L) -----------------------
__global__ void k_scan(const float* __restrict__ Alog)
{
    int b = blockIdx.x;
    int d = blockIdx.y * 64 + threadIdx.x;

    bool fast = true;
    float a[DS];
    #pragma unroll
    for (int s = 0; s < DS; s++) {
        a[s] = -expf(Alog[d * DS + s]);
        if (fabsf(a[s] + (float)(s + 1)) > 1e-4f * (float)(s + 1)) fast = false;
    }
    float h[DS];
    #pragma unroll
    for (int s = 0; s < DS; s++) h[s] = 0.f;

    const float*  bcp = g_dbl + (size_t)b * Lsz * 40;
    const float2* pwp = (const float2*)g_pw + ((size_t)b * Lsz * DI + d);
    float*        yp  = g_y + (size_t)b * Lsz * DI + d;

    if (fast) {
        for (int l = 0; l < Lsz; l++) {
            float2 pv = pwp[(size_t)l * DI];
            const float4* B4 = (const float4*)(bcp + (size_t)l * 40 + 8);
            const float4* C4 = (const float4*)(bcp + (size_t)l * 40 + 24);
            float p = pv.x, w = pv.y;
            float p2 = p * p;
            float q1 = p, q2 = p2, q3 = p2 * p, q4 = p2 * p2;
            float y0 = 0.f, y1 = 0.f, y2 = 0.f, y3 = 0.f;
            float base = 1.f;
            #pragma unroll
            for (int g = 0; g < 4; g++) {
                float4 Bv = B4[g], Cv = C4[g];
                float d1 = base*q1, d2 = base*q2, d3 = base*q3, d4 = base*q4;
                h[4*g+0] = d1*h[4*g+0] + w*Bv.x;
                h[4*g+1] = d2*h[4*g+1] + w*Bv.y;
                h[4*g+2] = d3*h[4*g+2] + w*Bv.z;
                h[4*g+3] = d4*h[4*g+3] + w*Bv.w;
                y0 += h[4*g+0]*Cv.x;
                y1 += h[4*g+1]*Cv.y;
                y2 += h[4*g+2]*Cv.z;
                y3 += h[4*g+3]*Cv.w;
                base = base * q4;
            }
            yp[(size_t)l * DI] = (y0 + y1) + (y2 + y3);
        }
    } else {
        for (int l = 0; l < Lsz; l++) {
            float2 pv = pwp[(size_t)l * DI];
            float w = pv.y;
            float dt = -__logf(fmaxf(pv.x, 1e-38f));
            float yacc = 0.f;
            #pragma unroll
            for (int s = 0; s < DS; s++) {
                float dA = __expf(dt * a[s]);
                h[s] = dA*h[s] + w * bcp[(size_t)l * 40 + 8 + s];
                yacc += h[s] * bcp[(size_t)l * 40 + 24 + s];
            }
            yp[(size_t)l * DI] = yacc;
        }
    }
}

// ---------------- masked mean pool: 2-stage ---------------------------------
__global__ void k_pool1(const float* __restrict__ mask)
{
    int b = blockIdx.x, s = blockIdx.y;
    int e = threadIdx.x;
    const float* xp = g_x + ((size_t)b * Lsz + s * 128) * DM + e;
    const float* mp = mask + (size_t)b * Lsz + s * 128;
    float acc = 0.f, ms = 0.f;
    for (int l = 0; l < 128; l++) {
        float m = mp[l];
        acc += xp[(size_t)l * DM] * m;
        ms += m;
    }
    g_poolp[(b * 16 + s) * DM + e] = acc;
    if (e == 0) g_msum[b * 16 + s] = ms;
}
__global__ void k_pool2()
{
    int b = blockIdx.x, e = threadIdx.x;
    float acc = 0.f, ms = 0.f;
    for (int s = 0; s < 16; s++) {
        acc += g_poolp[(b * 16 + s) * DM + e];
        ms += g_msum[b * 16 + s];
    }
    g_pool[b * DM + e] = acc / fmaxf(ms, 1e-9f);
}

// ---------------- final 512 -> 3 head ---------------------------------------
__global__ void k_mlp3(const float* __restrict__ w, const float* __restrict__ bias,
                       float* __restrict__ out)
{
    int t = threadIdx.x;
    if (t >= Bsz * 3) return;
    int bb = t / 3, n = t - bb * 3;
    const float* hp = g_h2 + bb * 512;
    const float* wp = w + n * 512;
    float acc = bias[n];
    for (int k = 0; k < 512; k++) acc += hp[k] * wp[k];
    out[bb * 3 + n] = acc;
}

// ---------------- launch ----------------------------------------------------
extern "C" void kernel_launch(void* const* d_in, const int* in_sizes, int n_in,
                              void* d_out, int out_size)
{
    const int*   tokens = (const int*)  d_in[0];
    const float* mask   = (const float*)d_in[1];
    const float* emb    = (const float*)d_in[2];
    const float* bn_w   = (const float*)d_in[3];
    const float* bn_b   = (const float*)d_in[4];
    const float* conv_w = (const float*)d_in[5];
    const float* conv_b = (const float*)d_in[6];
    const float* in_w   = (const float*)d_in[7];
    const float* c1_w   = (const float*)d_in[8];
    const float* c1_b   = (const float*)d_in[9];
    const float* xp_w   = (const float*)d_in[10];
    const float* dtp_w  = (const float*)d_in[11];
    const float* dtp_b  = (const float*)d_in[12];
    const float* A_log  = (const float*)d_in[13];
    const float* D_p    = (const float*)d_in[14];
    const float* out_w  = (const float*)d_in[15];
    const float* norm_w = (const float*)d_in[16];
    const float* l1w    = (const float*)d_in[17];
    const float* l1b    = (const float*)d_in[18];
    const float* l2w    = (const float*)d_in[19];
    const float* l2b    = (const float*)d_in[20];
    const float* l3w    = (const float*)d_in[21];
    const float* l3b    = (const float*)d_in[22];
    float* out = (float*)d_out;

    float *p_xn, *p_x, *p_xz, *p_xc, *p_dbl, *p_y, *p_pool, *p_h1, *p_h2, *p_wext;
    cudaGetSymbolAddress((void**)&p_xn,  g_xn);
    cudaGetSymbolAddress((void**)&p_x,   g_x);
    cudaGetSymbolAddress((void**)&p_xz,  g_xz);
    cudaGetSymbolAddress((void**)&p_xc,  g_xc);
    cudaGetSymbolAddress((void**)&p_dbl, g_dbl);
    cudaGetSymbolAddress((void**)&p_y,   g_y);
    cudaGetSymbolAddress((void**)&p_pool,g_pool);
    cudaGetSymbolAddress((void**)&p_h1,  g_h1);
    cudaGetSymbolAddress((void**)&p_h2,  g_h2);
    cudaGetSymbolAddress((void**)&p_wext,g_wext);

    const int SMB = 65536;
    cudaFuncSetAttribute(k_hmm, cudaFuncAttributeMaxDynamicSharedMemorySize, SMB);

    k_embed<<<BL * EMBD / 256, 256>>>(tokens, emb, bn_w, bn_b);
    k_repack<<<(DM * 384 + 255) / 256, 256>>>(conv_w);
    // front conv: implicit GEMM, K=384, N=128, bias+relu -> g_x
    k_hmm<<<dim3(BL / 128, 1), 256, SMB>>>(p_xn, p_wext, (const float*)0, conv_b,
                                           (const float*)0, p_x,
                                           384, 128, 128, 128, 2, 1);

    for (int i = 0; i < NL; i++) {
        k_rms<<<BL / 8, 256>>>(norm_w + (size_t)i * DM);
        // in_proj: [BL,128] x [512,128]^T -> g_xz
        k_hmm<<<dim3(BL / 128, 4), 256, SMB>>>(p_xn, in_w + (size_t)i * 512 * DM,
                                               (const float*)0, (const float*)0,
                                               (const float*)0, p_xz,
                                               128, 512, 512, 512, 0, 0);
        k_dwconv<<<dim3(Lsz / 16, Bsz), 256>>>(c1_w + (size_t)i * DI * 4, c1_b + (size_t)i * DI);
        // x_proj: [BL,256] x [40,256]^T -> g_dbl
        k_hmm<<<dim3(BL / 128, 1), 256, SMB>>>(p_xc, xp_w + (size_t)i * 40 * DI,
                                               (const float*)0, (const float*)0,
                                               (const float*)0, p_dbl,
                                               256, 40, 40, 40, 0, 0);
        k_dt<<<BL, 256>>>(dtp_w + (size_t)i * DI * DR, dtp_b + (size_t)i * DI);
        k_scan<<<dim3(Bsz, DI / 64), 64>>>(A_log + (size_t)i * DI * DS);
        // out_proj with fused gate: A = (y + u*D)*silu(z); += residual g_x
        k_hmm<<<dim3(BL / 128, 1), 256, SMB>>>(p_y, out_w + (size_t)i * DM * DI,
                                               D_p + (size_t)i * DI, (const float*)0,
                                               p_x, p_x,
                                               256, 128, 128, 128, 1, 0);
    }

    k_pool1<<<dim3(Bsz, 16), 128>>>(mask);
    k_pool2<<<Bsz, 128>>>();
    k_gemm<<<dim3(1, 512 / 64), 256>>>(p_pool, l1w, l1b, (const float*)0, p_h1, 512, DM, 1);
    k_gemm<<<dim3(1, 512 / 64), 256>>>(p_h1,   l2w, l2b, (const float*)0, p_h2, 512, 512, 1);
    k_mlp3<<<1, 256>>>(l3w, l3b, out);
}

// round 4
// speedup vs baseline: 2.2742x; 1.6950x over previous
#include <cuda_runtime.h>
#include <cuda_bf16.h>
#include <math.h>
#include <stdint.h>

#define Bsz 64
#define Lsz 2048
#define BL (Bsz*Lsz)      // 131072
#define EMBD 128
#define DM 128
#define DI 256
#define DS 16
#define DR 8
#define NL 4
#define NCH 32            // scan chunks
#define CLEN 64           // chunk length

// ---------------- scratch (static device arrays; no cudaMalloc) ------------
__device__ float g_xn[BL*DM];          // embed output / rmsnorm output
__device__ float g_x [BL*DM];          // residual stream
__device__ float g_xz[(size_t)BL*512]; // in_proj out: [..:256]=xi, [256:]=z
__device__ float g_xc[(size_t)BL*DI];  // depthwise conv + silu = u
__device__ float g_dbl[(size_t)BL*40]; // x_proj out (dtlow|B|C)
__device__ float g_y [(size_t)BL*DI];  // scan out
__device__ float g_hc[(size_t)Bsz*NCH*DI*DS]; // chunk states
__device__ float g_sd[(size_t)Bsz*NCH*DI];    // chunk sum(dt)
__device__ float g_wext[DM*384];       // repacked front conv weight
__device__ float g_pool[Bsz*DM];
__device__ float g_poolp[Bsz*16*DM];
__device__ float g_msum[Bsz*16];
__device__ float g_h1[Bsz*512];
__device__ float g_h2[Bsz*512];

// =================== mma.sync helpers (portable sm_80+ PTX) ================
__device__ __forceinline__ uint32_t s2u(const void* p) {
    uint32_t a;
    asm("{ .reg .u64 t; cvta.to.shared.u64 t, %1; cvt.u32.u64 %0, t; }" : "=r"(a) : "l"(p));
    return a;
}
__device__ __forceinline__ uint32_t swz(uint32_t off) {   // SW128 swizzle
    return off ^ ((off >> 3) & 0x70);
}
__device__ __forceinline__ void ldm_x4(uint32_t* r, uint32_t addr) {
    asm volatile("ldmatrix.sync.aligned.m8n8.x4.shared.b16 {%0,%1,%2,%3}, [%4];"
        : "=r"(r[0]), "=r"(r[1]), "=r"(r[2]), "=r"(r[3]) : "r"(addr));
}
__device__ __forceinline__ void mma_bf16(float* d, const uint32_t* a, const uint32_t* b) {
    asm volatile(
        "mma.sync.aligned.m16n8k16.row.col.f32.bf16.bf16.f32 "
        "{%0,%1,%2,%3}, {%4,%5,%6,%7}, {%8,%9}, {%0,%1,%2,%3};"
        : "+f"(d[0]), "+f"(d[1]), "+f"(d[2]), "+f"(d[3])
        : "r"(a[0]), "r"(a[1]), "r"(a[2]), "r"(a[3]), "r"(b[0]), "r"(b[1]));
}
__device__ __forceinline__ uint32_t pack_bf2(__nv_bfloat16 a, __nv_bfloat16 b) {
    unsigned short x = *(unsigned short*)&a, y = *(unsigned short*)&b;
    return (uint32_t)x | ((uint32_t)y << 16);
}
__device__ __forceinline__ void stash(char* hi, char* lo, int row, int col4, float4 v) {
    __nv_bfloat16 h0 = __float2bfloat16(v.x), h1 = __float2bfloat16(v.y);
    __nv_bfloat16 h2 = __float2bfloat16(v.z), h3 = __float2bfloat16(v.w);
    float l0 = v.x - __bfloat162float(h0), l1 = v.y - __bfloat162float(h1);
    float l2 = v.z - __bfloat162float(h2), l3 = v.w - __bfloat162float(h3);
    __nv_bfloat16 g0 = __float2bfloat16(l0), g1 = __float2bfloat16(l1);
    __nv_bfloat16 g2 = __float2bfloat16(l2), g3 = __float2bfloat16(l3);
    uint32_t off = (uint32_t)(row * 128 + col4 * 2);
    uint32_t sw = swz(off);
    *(uint2*)(hi + sw) = make_uint2(pack_bf2(h0, h1), pack_bf2(h2, h3));
    *(uint2*)(lo + sw) = make_uint2(pack_bf2(g0, g1), pack_bf2(g2, g3));
}

// ============== tensor-core split-bf16 GEMM via mma.sync ====================
__global__ void __launch_bounds__(256, 2)
k_hmm(const float* __restrict__ A, const float* __restrict__ W,
      const float* __restrict__ Dp, const float* __restrict__ bias,
      const float* __restrict__ res, float* __restrict__ C,
      int K, int ldC, int Nreal, int Nstore, int amode, int relu)
{
    extern __shared__ char smem[];
    char* AH = smem;
    char* AL = smem + 16384;
    char* BH = smem + 32768;
    char* BLo = smem + 49152;
    uint32_t uAH = s2u(AH), uAL = s2u(AL), uBH = s2u(BH), uBL = s2u(BLo);

    int tid = threadIdx.x;
    int wid = tid >> 5, lane = tid & 31;
    int mw = wid & 3, nw = wid >> 2;
    long bm = (long)blockIdx.x * 128;
    int bn = blockIdx.y * 128;

    int cg = tid & 15, rb = tid >> 4;
    int col4 = cg * 4;

    int lmat = lane >> 3, lrow = lane & 7;
    int a_row = mw * 32 + (lmat & 1) * 8 + lrow;
    int a_koff = (lmat >> 1) * 16;
    int b_row = nw * 64 + (lmat >> 1) * 8 + lrow;
    int b_koff = (lmat & 1) * 16;

    bool wact = (bn + nw * 64) < Nreal;   // whole warp-col out of range?

    float acc[2][8][4];
    #pragma unroll
    for (int f = 0; f < 2; f++)
        #pragma unroll
        for (int n = 0; n < 8; n++)
            #pragma unroll
            for (int j = 0; j < 4; j++) acc[f][n][j] = 0.f;

    int KB = K / 64;
    for (int kb = 0; kb < KB; kb++) {
        #pragma unroll
        for (int i = 0; i < 8; i++) {
            int row = rb + i * 16;
            float4 v;
            if (amode == 0) {
                v = *(const float4*)(A + (size_t)(bm + row) * K + kb * 64 + col4);
            } else if (amode == 1) {
                size_t off = (size_t)(bm + row) * 256 + kb * 64 + col4;
                float4 yv = *(const float4*)(g_y + off);
                float4 uv = *(const float4*)(g_xc + off);
                float4 zv = *(const float4*)(g_xz + (size_t)(bm + row) * 512 + 256 + kb * 64 + col4);
                float4 dv = *(const float4*)(Dp + kb * 64 + col4);
                v.x = (yv.x + uv.x * dv.x) * (zv.x / (1.f + __expf(-zv.x)));
                v.y = (yv.y + uv.y * dv.y) * (zv.y / (1.f + __expf(-zv.y)));
                v.z = (yv.z + uv.z * dv.z) * (zv.z / (1.f + __expf(-zv.z)));
                v.w = (yv.w + uv.w * dv.w) * (zv.w / (1.f + __expf(-zv.w)));
            } else {
                int tap = kb >> 1;
                int e = (kb & 1) * 64 + col4;
                long m = bm + row;
                int l = (int)(m & (Lsz - 1));
                int lsrc = l + tap - 1;
                if (lsrc >= 0 && lsrc < Lsz)
                    v = *(const float4*)(A + (size_t)(m + tap - 1) * 128 + e);
                else
                    v = make_float4(0.f, 0.f, 0.f, 0.f);
            }
            stash(AH, AL, row, col4, v);
        }
        #pragma unroll
        for (int i = 0; i < 8; i++) {
            int n = rb + i * 16;
            float4 v = make_float4(0.f, 0.f, 0.f, 0.f);
            if (bn + n < Nreal)
                v = *(const float4*)(W + (size_t)(bn + n) * K + kb * 64 + col4);
            stash(BH, BLo, n, col4, v);
        }
        __syncthreads();

        if (wact) {
            #pragma unroll
            for (int kk = 0; kk < 4; kk++) {
                uint32_t ah[2][4], al[2][4];
                #pragma unroll
                for (int f = 0; f < 2; f++) {
                    uint32_t off = (uint32_t)((a_row + f * 16) * 128 + kk * 32 + a_koff);
                    uint32_t sw = swz(off);
                    ldm_x4(ah[f], uAH + sw);
                    ldm_x4(al[f], uAL + sw);
                }
                #pragma unroll
                for (int np = 0; np < 4; np++) {
                    uint32_t bh[4], bl[4];
                    uint32_t off = (uint32_t)((b_row + np * 16) * 128 + kk * 32 + b_koff);
                    uint32_t sw = swz(off);
                    ldm_x4(bh, uBH + sw);
                    ldm_x4(bl, uBL + sw);
                    #pragma unroll
                    for (int f = 0; f < 2; f++) {
                        mma_bf16(acc[f][2*np+0], ah[f], bh + 0);
                        mma_bf16(acc[f][2*np+0], ah[f], bl + 0);
                        mma_bf16(acc[f][2*np+0], al[f], bh + 0);
                        mma_bf16(acc[f][2*np+1], ah[f], bh + 2);
                        mma_bf16(acc[f][2*np+1], ah[f], bl + 2);
                        mma_bf16(acc[f][2*np+1], al[f], bh + 2);
                    }
                }
            }
        }
        __syncthreads();
    }

    int g = lane >> 2, t2 = (lane & 3) * 2;
    #pragma unroll
    for (int f = 0; f < 2; f++) {
        #pragma unroll
        for (int nt = 0; nt < 8; nt++) {
            int col = bn + nw * 64 + nt * 8 + t2;
            if (col >= Nstore) continue;
            long r0 = bm + mw * 32 + f * 16 + g;
            long r1 = r0 + 8;
            float2 d0 = make_float2(acc[f][nt][0], acc[f][nt][1]);
            float2 d1 = make_float2(acc[f][nt][2], acc[f][nt][3]);
            if (bias) { float b0 = bias[col], b1 = bias[col+1];
                        d0.x += b0; d0.y += b1; d1.x += b0; d1.y += b1; }
            if (res) {
                float2 q0 = *(const float2*)(res + (size_t)r0 * ldC + col);
                float2 q1 = *(const float2*)(res + (size_t)r1 * ldC + col);
                d0.x += q0.x; d0.y += q0.y; d1.x += q1.x; d1.y += q1.y;
            }
            if (relu) {
                d0.x = fmaxf(d0.x, 0.f); d0.y = fmaxf(d0.y, 0.f);
                d1.x = fmaxf(d1.x, 0.f); d1.y = fmaxf(d1.y, 0.f);
            }
            *(float2*)(C + (size_t)r0 * ldC + col) = d0;
            *(float2*)(C + (size_t)r1 * ldC + col) = d1;
        }
    }
}

// ---------------- embed + batchnorm-ish scale -----------------------------
__global__ void k_embed(const int* __restrict__ tok, const float* __restrict__ emb,
                        const float* __restrict__ bnw, const float* __restrict__ bnb)
{
    int idx = blockIdx.x * 256 + threadIdx.x;
    if (idx >= BL * EMBD) return;
    int e = idx & 127;
    int t = idx >> 7;
    float s = bnw[e] * rsqrtf(1.0f + 1e-5f);
    g_xn[idx] = emb[tok[t] * EMBD + e] * s + bnb[e];
}

__global__ void k_repack(const float* __restrict__ cw)
{
    int idx = blockIdx.x * 256 + threadIdx.x;
    if (idx >= DM * 384) return;
    int o = idx / 384, kg = idx % 384;
    int tap = kg >> 7, e = kg & 127;
    g_wext[idx] = cw[(o * EMBD + e) * 3 + tap];
}

// ---------------- rmsnorm: warp per row, float4 ----------------------------
__global__ void k_rms(const float* __restrict__ nw)
{
    int w = threadIdx.x >> 5, lid = threadIdx.x & 31;
    long row = (long)blockIdx.x * 8 + w;
    float4 v = ((const float4*)(g_x + row * DM))[lid];
    float ss = v.x * v.x + v.y * v.y + v.z * v.z + v.w * v.w;
    #pragma unroll
    for (int o = 16; o; o >>= 1) ss += __shfl_xor_sync(0xffffffffu, ss, o);
    float r = rsqrtf(ss * (1.f / DM) + 1e-5f);
    float4 wv = ((const float4*)nw)[lid];
    float4 ov = make_float4(v.x * r * wv.x, v.y * r * wv.y, v.z * r * wv.z, v.w * r * wv.w);
    ((float4*)(g_xn + row * DM))[lid] = ov;
}

// ---------------- generic fp32 GEMM (small head layers) --------------------
__global__ void k_gemm(const float* __restrict__ A, const float* __restrict__ W,
                       const float* __restrict__ bias, const float* __restrict__ res,
                       float* __restrict__ C, int N, int K, int act)
{
    __shared__ float As[16][64];
    __shared__ float Ws[16][64];
    int tid = threadIdx.x;
    int tx = tid & 15, ty = tid >> 4;
    long bm = (long)blockIdx.x * 64;
    int bn = blockIdx.y * 64;
    int lrow = tid >> 2, lcol = (tid & 3) * 4;
    const float* Ap = A + (bm + lrow) * (size_t)K + lcol;
    int nrow = bn + lrow;
    const float* Wp = (nrow < N) ? (W + (size_t)nrow * K + lcol) : (const float*)0;
    float acc[4][4] = {};
    for (int kc = 0; kc < K; kc += 16) {
        float4 av = *(const float4*)(Ap + kc);
        float4 wv = make_float4(0.f, 0.f, 0.f, 0.f);
        if (Wp) wv = *(const float4*)(Wp + kc);
        As[lcol+0][lrow]=av.x; As[lcol+1][lrow]=av.y; As[lcol+2][lrow]=av.z; As[lcol+3][lrow]=av.w;
        Ws[lcol+0][lrow]=wv.x; Ws[lcol+1][lrow]=wv.y; Ws[lcol+2][lrow]=wv.z; Ws[lcol+3][lrow]=wv.w;
        __syncthreads();
        #pragma unroll
        for (int kk = 0; kk < 16; kk++) {
            float4 a4 = *(const float4*)&As[kk][ty*4];
            float4 w4 = *(const float4*)&Ws[kk][tx*4];
            acc[0][0]+=a4.x*w4.x; acc[0][1]+=a4.x*w4.y; acc[0][2]+=a4.x*w4.z; acc[0][3]+=a4.x*w4.w;
            acc[1][0]+=a4.y*w4.x; acc[1][1]+=a4.y*w4.y; acc[1][2]+=a4.y*w4.z; acc[1][3]+=a4.y*w4.w;
            acc[2][0]+=a4.z*w4.x; acc[2][1]+=a4.z*w4.y; acc[2][2]+=a4.z*w4.z; acc[2][3]+=a4.z*w4.w;
            acc[3][0]+=a4.w*w4.x; acc[3][1]+=a4.w*w4.y; acc[3][2]+=a4.w*w4.z; acc[3][3]+=a4.w*w4.w;
        }
        __syncthreads();
    }
    #pragma unroll
    for (int i = 0; i < 4; i++) {
        long row = bm + ty * 4 + i;
        #pragma unroll
        for (int j = 0; j < 4; j++) {
            int col = bn + tx * 4 + j;
            if (col < N) {
                float v = acc[i][j];
                if (bias) v += bias[col];
                if (res)  v += res[row * (size_t)N + col];
                if (act)  v = fmaxf(v, 0.f);
                C[row * (size_t)N + col] = v;
            }
        }
    }
}

// ---------------- depthwise causal conv (k=4) + silu -----------------------
__global__ void k_dwconv(const float* __restrict__ w, const float* __restrict__ bias)
{
    int b  = blockIdx.y;
    int l0 = blockIdx.x * 16;
    int d  = threadIdx.x;
    float w0 = w[d*4+0], w1 = w[d*4+1], w2 = w[d*4+2], w3 = w[d*4+3];
    float bb = bias[d];
    const float* xp = g_xz + (size_t)b * Lsz * 512 + d;
    float v[19];
    #pragma unroll
    for (int j = 0; j < 19; j++) {
        int ls = l0 + j - 3;
        v[j] = (ls >= 0) ? xp[(size_t)ls * 512] : 0.f;
    }
    float* op = g_xc + ((size_t)b * Lsz + l0) * DI + d;
    #pragma unroll
    for (int t = 0; t < 16; t++) {
        float a = v[t]*w0 + v[t+1]*w1 + v[t+2]*w2 + v[t+3]*w3 + bb;
        op[(size_t)t * DI] = a / (1.f + __expf(-a));
    }
}

// ================= chunked selective scan ===================================
// dt/p computed inline from g_dbl (dtlow) + dtp weights; u from g_xc.
__device__ __forceinline__ void dt_inline(const float* __restrict__ row,
                                          float4 w0, float4 w1, float bd,
                                          float& dt, float& p)
{
    float4 r0 = *(const float4*)(row);
    float4 r1 = *(const float4*)(row + 4);
    float a = bd + r0.x*w0.x + r0.y*w0.y + r0.z*w0.z + r0.w*w0.w
                 + r1.x*w1.x + r1.y*w1.y + r1.z*w1.z + r1.w*w1.w;
    dt = (a > 15.f) ? a : log1pf(__expf(a));
    p  = 1.f / (1.f + __expf(a));
}

// pass A: local scan (h from 0), store h_end[16] and sum(dt)
__global__ void __launch_bounds__(256)
k_scanA(const float* __restrict__ Alog,
        const float* __restrict__ dtw, const float* __restrict__ dtb)
{
    int c = blockIdx.x, b = blockIdx.y, d = threadIdx.x;
    float4 w0 = ((const float4*)(dtw + d * 8))[0];
    float4 w1 = ((const float4*)(dtw + d * 8))[1];
    float bd = dtb[d];

    bool fast = true;
    float a[DS];
    #pragma unroll
    for (int s = 0; s < DS; s++) {
        a[s] = -expf(Alog[d * DS + s]);
        if (fabsf(a[s] + (float)(s + 1)) > 1e-4f * (float)(s + 1)) fast = false;
    }
    float h[DS];
    #pragma unroll
    for (int s = 0; s < DS; s++) h[s] = 0.f;
    float sumdt = 0.f;

    const float* dblp = g_dbl + ((size_t)b * Lsz + c * CLEN) * 40;
    const float* up   = g_xc  + ((size_t)b * Lsz + c * CLEN) * DI + d;

    if (fast) {
        for (int l = 0; l < CLEN; l++) {
            float dt, p;
            dt_inline(dblp + (size_t)l * 40, w0, w1, bd, dt, p);
            float w = dt * up[(size_t)l * DI];
            sumdt += dt;
            const float4* B4 = (const float4*)(dblp + (size_t)l * 40 + 8);
            float p2 = p * p;
            float q1 = p, q2 = p2, q3 = p2 * p, q4 = p2 * p2;
            float base = 1.f;
            #pragma unroll
            for (int g = 0; g < 4; g++) {
                float4 Bv = B4[g];
                h[4*g+0] = (base*q1)*h[4*g+0] + w*Bv.x;
                h[4*g+1] = (base*q2)*h[4*g+1] + w*Bv.y;
                h[4*g+2] = (base*q3)*h[4*g+2] + w*Bv.z;
                h[4*g+3] = (base*q4)*h[4*g+3] + w*Bv.w;
                base = base * q4;
            }
        }
    } else {
        for (int l = 0; l < CLEN; l++) {
            float dt, p;
            dt_inline(dblp + (size_t)l * 40, w0, w1, bd, dt, p);
            float w = dt * up[(size_t)l * DI];
            sumdt += dt;
            #pragma unroll
            for (int s = 0; s < DS; s++) {
                float dA = __expf(dt * a[s]);
                h[s] = dA * h[s] + w * dblp[(size_t)l * 40 + 8 + s];
            }
        }
    }
    float* slot = g_hc + (((size_t)b * NCH + c) * DI + d) * DS;
    #pragma unroll
    for (int q = 0; q < 4; q++)
        ((float4*)slot)[q] = make_float4(h[4*q], h[4*q+1], h[4*q+2], h[4*q+3]);
    g_sd[((size_t)b * NCH + c) * DI + d] = sumdt;
}

// pass B: prefix over chunks; g_hc slot becomes chunk START state
__global__ void __launch_bounds__(256)
k_scanB(const float* __restrict__ Alog)
{
    int b = blockIdx.x, d = threadIdx.x;
    float a[DS];
    #pragma unroll
    for (int s = 0; s < DS; s++) a[s] = -expf(Alog[d * DS + s]);
    float hp[DS];
    #pragma unroll
    for (int s = 0; s < DS; s++) hp[s] = 0.f;

    for (int c = 0; c < NCH; c++) {
        float* slot = g_hc + (((size_t)b * NCH + c) * DI + d) * DS;
        float sd = g_sd[((size_t)b * NCH + c) * DI + d];
        float hl[DS];
        #pragma unroll
        for (int q = 0; q < 4; q++) {
            float4 v = ((const float4*)slot)[q];
            hl[4*q] = v.x; hl[4*q+1] = v.y; hl[4*q+2] = v.z; hl[4*q+3] = v.w;
        }
        #pragma unroll
        for (int q = 0; q < 4; q++)
            ((float4*)slot)[q] = make_float4(hp[4*q], hp[4*q+1], hp[4*q+2], hp[4*q+3]);
        #pragma unroll
        for (int s = 0; s < DS; s++)
            hp[s] = __expf(a[s] * sd) * hp[s] + hl[s];
    }
}

// pass C: re-run local scan from true start state, emit y
__global__ void __launch_bounds__(256)
k_scanC(const float* __restrict__ Alog,
        const float* __restrict__ dtw, const float* __restrict__ dtb)
{
    int c = blockIdx.x, b = blockIdx.y, d = threadIdx.x;
    float4 w0 = ((const float4*)(dtw + d * 8))[0];
    float4 w1 = ((const float4*)(dtw + d * 8))[1];
    float bd = dtb[d];

    bool fast = true;
    float a[DS];
    #pragma unroll
    for (int s = 0; s < DS; s++) {
        a[s] = -expf(Alog[d * DS + s]);
        if (fabsf(a[s] + (float)(s + 1)) > 1e-4f * (float)(s + 1)) fast = false;
    }
    float h[DS];
    const float* slot = g_hc + (((size_t)b * NCH + c) * DI + d) * DS;
    #pragma unroll
    for (int q = 0; q < 4; q++) {
        float4 v = ((const float4*)slot)[q];
        h[4*q] = v.x; h[4*q+1] = v.y; h[4*q+2] = v.z; h[4*q+3] = v.w;
    }

    const float* dblp = g_dbl + ((size_t)b * Lsz + c * CLEN) * 40;
    const float* up   = g_xc  + ((size_t)b * Lsz + c * CLEN) * DI + d;
    float*       yp   = g_y   + ((size_t)b * Lsz + c * CLEN) * DI + d;

    if (fast) {
        for (int l = 0; l < CLEN; l++) {
            float dt, p;
            dt_inline(dblp + (size_t)l * 40, w0, w1, bd, dt, p);
            float w = dt * up[(size_t)l * DI];
            const float4* B4 = (const float4*)(dblp + (size_t)l * 40 + 8);
            const float4* C4 = (const float4*)(dblp + (size_t)l * 40 + 24);
            float p2 = p * p;
            float q1 = p, q2 = p2, q3 = p2 * p, q4 = p2 * p2;
            float y0 = 0.f, y1 = 0.f, y2 = 0.f, y3 = 0.f;
            float base = 1.f;
            #pragma unroll
            for (int g = 0; g < 4; g++) {
                float4 Bv = B4[g], Cv = C4[g];
                h[4*g+0] = (base*q1)*h[4*g+0] + w*Bv.x;
                h[4*g+1] = (base*q2)*h[4*g+1] + w*Bv.y;
                h[4*g+2] = (base*q3)*h[4*g+2] + w*Bv.z;
                h[4*g+3] = (base*q4)*h[4*g+3] + w*Bv.w;
                y0 += h[4*g+0]*Cv.x;
                y1 += h[4*g+1]*Cv.y;
                y2 += h[4*g+2]*Cv.z;
                y3 += h[4*g+3]*Cv.w;
                base = base * q4;
            }
            yp[(size_t)l * DI] = (y0 + y1) + (y2 + y3);
        }
    } else {
        for (int l = 0; l < CLEN; l++) {
            float dt, p;
            dt_inline(dblp + (size_t)l * 40, w0, w1, bd, dt, p);
            float w = dt * up[(size_t)l * DI];
            float yacc = 0.f;
            #pragma unroll
            for (int s = 0; s < DS; s++) {
                float dA = __expf(dt * a[s]);
                h[s] = dA * h[s] + w * dblp[(size_t)l * 40 + 8 + s];
                yacc += h[s] * dblp[(size_t)l * 40 + 24 + s];
            }
            yp[(size_t)l * DI] = yacc;
        }
    }
}

// ---------------- masked mean pool: 2-stage ---------------------------------
__global__ void k_pool1(const float* __restrict__ mask)
{
    int b = blockIdx.x, s = blockIdx.y;
    int e = threadIdx.x;
    const float* xp = g_x + ((size_t)b * Lsz + s * 128) * DM + e;
    const float* mp = mask + (size_t)b * Lsz + s * 128;
    float acc = 0.f, ms = 0.f;
    for (int l = 0; l < 128; l++) {
        float m = mp[l];
        acc += xp[(size_t)l * DM] * m;
        ms += m;
    }
    g_poolp[(b * 16 + s) * DM + e] = acc;
    if (e == 0) g_msum[b * 16 + s] = ms;
}
__global__ void k_pool2()
{
    int b = blockIdx.x, e = threadIdx.x;
    float acc = 0.f, ms = 0.f;
    for (int s = 0; s < 16; s++) {
        acc += g_poolp[(b * 16 + s) * DM + e];
        ms += g_msum[b * 16 + s];
    }
    g_pool[b * DM + e] = acc / fmaxf(ms, 1e-9f);
}

__global__ void k_mlp3(const float* __restrict__ w, const float* __restrict__ bias,
                       float* __restrict__ out)
{
    int t = threadIdx.x;
    if (t >= Bsz * 3) return;
    int bb = t / 3, n = t - bb * 3;
    const float* hp = g_h2 + bb * 512;
    const float* wp = w + n * 512;
    float acc = bias[n];
    for (int k = 0; k < 512; k++) acc += hp[k] * wp[k];
    out[bb * 3 + n] = acc;
}

// ---------------- launch ----------------------------------------------------
extern "C" void kernel_launch(void* const* d_in, const int* in_sizes, int n_in,
                              void* d_out, int out_size)
{
    const int*   tokens = (const int*)  d_in[0];
    const float* mask   = (const float*)d_in[1];
    const float* emb    = (const float*)d_in[2];
    const float* bn_w   = (const float*)d_in[3];
    const float* bn_b   = (const float*)d_in[4];
    const float* conv_w = (const float*)d_in[5];
    const float* conv_b = (const float*)d_in[6];
    const float* in_w   = (const float*)d_in[7];
    const float* c1_w   = (const float*)d_in[8];
    const float* c1_b   = (const float*)d_in[9];
    const float* xp_w   = (const float*)d_in[10];
    const float* dtp_w  = (const float*)d_in[11];
    const float* dtp_b  = (const float*)d_in[12];
    const float* A_log  = (const float*)d_in[13];
    const float* D_p    = (const float*)d_in[14];
    const float* out_w  = (const float*)d_in[15];
    const float* norm_w = (const float*)d_in[16];
    const float* l1w    = (const float*)d_in[17];
    const float* l1b    = (const float*)d_in[18];
    const float* l2w    = (const float*)d_in[19];
    const float* l2b    = (const float*)d_in[20];
    const float* l3w    = (const float*)d_in[21];
    const float* l3b    = (const float*)d_in[22];
    float* out = (float*)d_out;

    float *p_xn, *p_x, *p_xz, *p_xc, *p_dbl, *p_y, *p_pool, *p_h1, *p_h2, *p_wext;
    cudaGetSymbolAddress((void**)&p_xn,  g_xn);
    cudaGetSymbolAddress((void**)&p_x,   g_x);
    cudaGetSymbolAddress((void**)&p_xz,  g_xz);
    cudaGetSymbolAddress((void**)&p_xc,  g_xc);
    cudaGetSymbolAddress((void**)&p_dbl, g_dbl);
    cudaGetSymbolAddress((void**)&p_y,   g_y);
    cudaGetSymbolAddress((void**)&p_pool,g_pool);
    cudaGetSymbolAddress((void**)&p_h1,  g_h1);
    cudaGetSymbolAddress((void**)&p_h2,  g_h2);
    cudaGetSymbolAddress((void**)&p_wext,g_wext);

    const int SMB = 65536;
    cudaFuncSetAttribute(k_hmm, cudaFuncAttributeMaxDynamicSharedMemorySize, SMB);

    k_embed<<<BL * EMBD / 256, 256>>>(tokens, emb, bn_w, bn_b);
    k_repack<<<(DM * 384 + 255) / 256, 256>>>(conv_w);
    k_hmm<<<dim3(BL / 128, 1), 256, SMB>>>(p_xn, p_wext, (const float*)0, conv_b,
                                           (const float*)0, p_x,
                                           384, 128, 128, 128, 2, 1);

    for (int i = 0; i < NL; i++) {
        const float* Al = A_log + (size_t)i * DI * DS;
        const float* dw = dtp_w + (size_t)i * DI * DR;
        const float* db = dtp_b + (size_t)i * DI;

        k_rms<<<BL / 8, 256>>>(norm_w + (size_t)i * DM);
        k_hmm<<<dim3(BL / 128, 4), 256, SMB>>>(p_xn, in_w + (size_t)i * 512 * DM,
                                               (const float*)0, (const float*)0,
                                               (const float*)0, p_xz,
                                               128, 512, 512, 512, 0, 0);
        k_dwconv<<<dim3(Lsz / 16, Bsz), 256>>>(c1_w + (size_t)i * DI * 4, c1_b + (size_t)i * DI);
        k_hmm<<<dim3(BL / 128, 1), 256, SMB>>>(p_xc, xp_w + (size_t)i * 40 * DI,
                                               (const float*)0, (const float*)0,
                                               (const float*)0, p_dbl,
                                               256, 40, 40, 40, 0, 0);
        k_scanA<<<dim3(NCH, Bsz), 256>>>(Al, dw, db);
        k_scanB<<<Bsz, 256>>>(Al);
        k_scanC<<<dim3(NCH, Bsz), 256>>>(Al, dw, db);
        k_hmm<<<dim3(BL / 128, 1), 256, SMB>>>(p_y, out_w + (size_t)i * DM * DI,
                                               D_p + (size_t)i * DI, (const float*)0,
                                               p_x, p_x,
                                               256, 128, 128, 128, 1, 0);
    }

    k_pool1<<<dim3(Bsz, 16), 128>>>(mask);
    k_pool2<<<Bsz, 128>>>();
    k_gemm<<<dim3(1, 512 / 64), 256>>>(p_pool, l1w, l1b, (const float*)0, p_h1, 512, DM, 1);
    k_gemm<<<dim3(1, 512 / 64), 256>>>(p_h1,   l2w, l2b, (const float*)0, p_h2, 512, 512, 1);
    k_mlp3<<<1, 256>>>(l3w, l3b, out);
}